// round 9
// baseline (speedup 1.0000x reference)
#include <cuda_runtime.h>
#include <cuda_bf16.h>

// Problem constants (match reference)
#define N_CLASSES   4
#define TIME_STEPS  120
#define BATCH       65536
#define NTHREADS    (BATCH * N_CLASSES)   // 262144: one thread per (batch, class)
#define DT_MS       10.0f
#define THRESH      0.5f
#define EPS_F       1e-9f
#define L2E_F       1.4426950408889634f   // log2(e)
#define LN2_F       0.6931471805599453f

__device__ __forceinline__ float fast_softplus(float x) {
    // parameter transform only (not in hot loop)
    float e = __expf(-fabsf(x));
    return fmaxf(x, 0.0f) + __logf(1.0f + e);
}

// One thread per (batch, class). Threads 4b..4b+3 (one lane quad) hold the 4
// classes of batch element b; quad sum via 3 independent shfl_xor.
// Noise is prefetched at DISTANCE 2 (two loads in flight per warp): at
// ~575 cycles wall per step, distance-1 left the single outstanding load
// racing the 577-cycle DRAM latency, locking the kernel at memory latency.
// Depth-2 gives ~1150 cycles of slack per load.
__global__ __launch_bounds__(256)
void acc_race_kernel(const float* __restrict__ logits,      // [B*4]
                     const float* __restrict__ p_iscale,
                     const float* __restrict__ p_leak,      // [4]
                     const float* __restrict__ p_se,        // [4]
                     const float* __restrict__ p_inh,
                     const float* __restrict__ p_ns,
                     const float* __restrict__ p_w,         // [1,1]
                     const float* __restrict__ p_b,         // [1]
                     const float* __restrict__ noise,       // [T*B*4]
                     float*       __restrict__ out)         // [B*4]
{
    const int tid = blockIdx.x * blockDim.x + threadIdx.x;
    const int c   = tid & (N_CLASSES - 1);

    // ---- parameters (broadcast loads; transform once) ----
    const float iscale = *p_iscale;
    const float w      = *p_w;
    const float bias   = *p_b;
    const float inh    = fast_softplus(*p_inh);
    const float ns     = fast_softplus(*p_ns);
    const float coefp = (fast_softplus(p_se[c]) + inh - fast_softplus(p_leak[c])) * L2E_F;
    const float inhp  = inh * L2E_F;
    const float nsp   = ns  * L2E_F;
    const float evp   = fmaf(fmaxf(logits[tid] * iscale, 0.0f), w, bias) * L2E_F;
    const float K     = 0.2f * LN2_F;   // Euler step absorbs base-2 scale

    // ---- rollout state ----
    float acc = 0.0f;
    float cp = 0.0f, cc = 0.0f, tc = 0.0f;  // crossPrev/crossCur (raw acc), step count
    bool  cr = false;

    // depth-2 noise prefetch pipeline (streaming loads, no L1 reuse)
    const float* np = noise + tid;
    float nzA = __ldcs(np);              // for step t
    np += NTHREADS;
    float nzB = __ldcs(np);              // for step t+1

#define STEP_BODY(NZ)                                                         \
    do {                                                                      \
        /* acc-independent part first: overlaps with the shuffles */          \
        const float evn = fmaf(nsp, (NZ), evp);                               \
        const float t1 = __shfl_xor_sync(0xffffffffu, acc, 1);                \
        const float t2 = __shfl_xor_sync(0xffffffffu, acc, 2);                \
        const float t3 = __shfl_xor_sync(0xffffffffu, acc, 3);                \
        const float x  = fmaf(coefp, acc, evn);                               \
        const float total = (acc + t1) + (t2 + t3);                           \
        const float dp = fmaf(-inhp, total, x);                               \
        const float sb = __log2f(1.0f + exp2f(dp));                           \
        acc = fmaxf(fmaf(K, sb, 0.8f * acc), 0.0f);                           \
        /* crossing bookkeeping: overwrite until crossed, then freeze */      \
        const bool nc = !cr;                                                  \
        cp = nc ? cc : cp;                                                    \
        cc = nc ? acc : cc;                                                   \
        tc = nc ? tc + 1.0f : tc;                                             \
        cr = cr || (acc >= THRESH);                                           \
    } while (0)

    // 118 pipelined iterations + 2 drained tails (loads stay 2 ahead)
#pragma unroll 2
    for (int t = 0; t < TIME_STEPS - 2; ++t) {
        np += NTHREADS;
        const float nzC = __ldcs(np);    // for step t+2
        STEP_BODY(nzA);
        nzA = nzB;
        nzB = nzC;
    }
    STEP_BODY(nzA);   // t = 118
    STEP_BODY(nzB);   // t = 119
#undef STEP_BODY

    // ---- epilogue: interpolate first-crossing time ----
    // prev = cp - THRESH, cur = cc - THRESH; THRESH cancels in denominator.
    float tm;
    if (cr) {
        const float idx = tc - 1.0f;    // first crossing index (float)
        tm = (idx > 0.0f)
               ? (idx - 1.0f + (THRESH - cp) / (cc - cp + EPS_F)) * DT_MS
               : 0.0f;                  // crossed at idx 0
    } else {
        tm = (float)TIME_STEPS * DT_MS; // never crossed: 1200 ms
    }
    out[tid] = tm * 0.001f;             // -> seconds
}

extern "C" void kernel_launch(void* const* d_in, const int* in_sizes, int n_in,
                              void* d_out, int out_size)
{
    const float* logits = (const float*)d_in[0];
    const float* iscale = (const float*)d_in[1];
    const float* leak   = (const float*)d_in[2];
    const float* se     = (const float*)d_in[3];
    const float* inh    = (const float*)d_in[4];
    const float* ns     = (const float*)d_in[5];
    const float* pw     = (const float*)d_in[6];
    const float* pb     = (const float*)d_in[7];
    const float* noise  = (const float*)d_in[8];
    float*       out    = (float*)d_out;

    const int threads = 256;
    const int blocks  = NTHREADS / threads;   // 1024
    acc_race_kernel<<<blocks, threads>>>(logits, iscale, leak, se, inh, ns,
                                         pw, pb, noise, out);
}

// round 12
// speedup vs baseline: 1.2323x; 1.2323x over previous
#include <cuda_runtime.h>
#include <cuda_bf16.h>

// Problem constants (match reference)
#define N_CLASSES   4
#define TIME_STEPS  120
#define BATCH       65536
#define NTHREADS    (BATCH * N_CLASSES)   // 262144: one thread per (batch, class)
#define DT_MS       10.0f
#define THRESH      0.5f
#define EPS_F       1e-9f
#define L2E_F       1.4426950408889634f   // log2(e)
#define LN2_F       0.6931471805599453f

__device__ __forceinline__ float ex2_approx(float x) {
    float r;
    asm("ex2.approx.ftz.f32 %0, %1;" : "=f"(r) : "f"(x));
    return r;
}
__device__ __forceinline__ float lg2_approx(float x) {
    float r;
    asm("lg2.approx.ftz.f32 %0, %1;" : "=f"(r) : "f"(x));
    return r;
}

__device__ __forceinline__ float fast_softplus(float x) {
    // parameter transform only (not in hot loop)
    float e = ex2_approx(-fabsf(x) * L2E_F);
    return fmaxf(x, 0.0f) + lg2_approx(1.0f + e) * LN2_F;
}

// One thread per (batch, class). Threads 4b..4b+3 (one lane quad) hold the 4
// classes of batch element b; quad sum via 3 independent shfl_xor.
//
// State is kept in the K-scaled domain z = acc / K with K = 0.2*ln2:
//   z' = max(0.8*z + sb, 0),  sb = log2(1 + 2^dp)      (one FMA, no FMUL)
//   dp = (coef*K*l2e)*z - (inh*K*l2e)*totz + ev*l2e + ns*l2e*noise
// All constants are folded at setup; softplus runs natively in base 2 through
// raw ex2/lg2 PTX (guaranteed single-MUFU regardless of compile flags).
__global__ __launch_bounds__(128)
void acc_race_kernel(const float* __restrict__ logits,      // [B*4]
                     const float* __restrict__ p_iscale,
                     const float* __restrict__ p_leak,      // [4]
                     const float* __restrict__ p_se,        // [4]
                     const float* __restrict__ p_inh,
                     const float* __restrict__ p_ns,
                     const float* __restrict__ p_w,         // [1,1]
                     const float* __restrict__ p_b,         // [1]
                     const float* __restrict__ noise,       // [T*B*4]
                     float*       __restrict__ out)         // [B*4]
{
    const int tid = blockIdx.x * blockDim.x + threadIdx.x;
    const int c   = tid & (N_CLASSES - 1);

    // ---- parameters (broadcast loads; transform once) ----
    const float iscale = *p_iscale;
    const float w      = *p_w;
    const float bias   = *p_b;
    const float inh    = fast_softplus(*p_inh);
    const float ns     = fast_softplus(*p_ns);
    const float K      = 0.2f * LN2_F;            // acc = K * z
    const float coefz  = (fast_softplus(p_se[c]) + inh - fast_softplus(p_leak[c]))
                         * L2E_F * K;             // multiplies z directly
    const float inhz   = inh * L2E_F * K;
    const float nsp    = ns  * L2E_F;
    const float evp    = fmaf(fmaxf(logits[tid] * iscale, 0.0f), w, bias) * L2E_F;
    const float ZTHRESH = THRESH / K;             // crossing test in z-domain

    // ---- rollout state (z-domain) ----
    float z  = 0.0f;
    float cp = 0.0f, cc = 0.0f, tc = 0.0f;  // crossPrev/crossCur (z), step count
    bool  cr = false;

    const float* np = noise + tid;
    float nz = *np;

#define STEP_BODY                                                             \
    do {                                                                      \
        /* acc-independent part first: overlaps with the shuffles */          \
        const float evn = fmaf(nsp, nz, evp);                                 \
        const float t1 = __shfl_xor_sync(0xffffffffu, z, 1);                  \
        const float t2 = __shfl_xor_sync(0xffffffffu, z, 2);                  \
        const float t3 = __shfl_xor_sync(0xffffffffu, z, 3);                  \
        const float x  = fmaf(coefz, z, evn);                                 \
        const float totz = (z + t1) + (t2 + t3);                              \
        const float dp = fmaf(-inhz, totz, x);                                \
        const float sb = lg2_approx(1.0f + ex2_approx(dp));                   \
        z = fmaxf(fmaf(0.8f, z, sb), 0.0f);                                   \
        /* crossing bookkeeping: overwrite until crossed, then freeze */      \
        const bool nc = !cr;                                                  \
        cp = nc ? cc : cp;                                                    \
        cc = nc ? z  : cc;                                                    \
        tc = nc ? tc + 1.0f : tc;                                             \
        cr = cr || (z >= ZTHRESH);                                            \
    } while (0)

    // 119 prefetching iterations (119 = 7*17, unrolls evenly) + 1 peeled tail
#pragma unroll 7
    for (int t = 0; t < TIME_STEPS - 1; ++t) {
        np += NTHREADS;
        const float nz_next = *np;
        STEP_BODY;
        nz = nz_next;
    }
    STEP_BODY;   // t = 119, no prefetch
#undef STEP_BODY

    // ---- epilogue: interpolate first-crossing time ----
    // acc = K*z everywhere, so the K cancels in frac's ratio:
    // frac = (THRESH/K - cp) / (cc - cp + eps')   with eps' = EPS/K.
    float tm;
    if (cr) {
        const float idx = tc - 1.0f;    // first crossing index (float)
        tm = (idx > 0.0f)
               ? (idx - 1.0f + (ZTHRESH - cp) / (cc - cp + EPS_F / K)) * DT_MS
               : 0.0f;                  // crossed at idx 0
    } else {
        tm = (float)TIME_STEPS * DT_MS; // never crossed: 1200 ms
    }
    out[tid] = tm * 0.001f;             // -> seconds
}

extern "C" void kernel_launch(void* const* d_in, const int* in_sizes, int n_in,
                              void* d_out, int out_size)
{
    const float* logits = (const float*)d_in[0];
    const float* iscale = (const float*)d_in[1];
    const float* leak   = (const float*)d_in[2];
    const float* se     = (const float*)d_in[3];
    const float* inh    = (const float*)d_in[4];
    const float* ns     = (const float*)d_in[5];
    const float* pw     = (const float*)d_in[6];
    const float* pb     = (const float*)d_in[7];
    const float* noise  = (const float*)d_in[8];
    float*       out    = (float*)d_out;

    const int threads = 128;                 // fine-grained CTAs: better SM balance
    const int blocks  = NTHREADS / threads;  // 2048
    acc_race_kernel<<<blocks, threads>>>(logits, iscale, leak, se, inh, ns,
                                         pw, pb, noise, out);
}

// round 13
// speedup vs baseline: 1.2357x; 1.0028x over previous
#include <cuda_runtime.h>
#include <cuda_bf16.h>

// Problem constants (match reference)
#define N_CLASSES   4
#define TIME_STEPS  120
#define BATCH       65536
#define NTHREADS    (BATCH * 2)          // 131072: one thread per (batch, class-pair)
#define ROW_F2      (BATCH * 2)          // float2 elements per timestep row
#define DT_MS       10.0f
#define THRESH      0.5f
#define EPS_F       1e-9f
#define L2E_F       1.4426950408889634f  // log2(e)
#define LN2_F       0.6931471805599453f

__device__ __forceinline__ float ex2_approx(float x) {
    float r;
    asm("ex2.approx.ftz.f32 %0, %1;" : "=f"(r) : "f"(x));
    return r;
}
__device__ __forceinline__ float lg2_approx(float x) {
    float r;
    asm("lg2.approx.ftz.f32 %0, %1;" : "=f"(r) : "f"(x));
    return r;
}

__device__ __forceinline__ float fast_softplus(float x) {
    // parameter transform only (not in hot loop)
    float e = ex2_approx(-fabsf(x) * L2E_F);
    return fmaxf(x, 0.0f) + lg2_approx(1.0f + e) * LN2_F;
}

// One thread per (batch, class-pair): thread tid handles flattened elements
// {2*tid, 2*tid+1}; its lane^1 partner holds the other class pair of the same
// batch element, so the 4-class sum is 1 local FADD + 1 shfl_xor + 1 FADD —
// 0.5 shuffles per element vs 3 in the 1-class layout (MIO pipe was ~43%
// busy there, dominated by SHFL).
//
// State in the K-scaled domain z = acc / K (K = 0.2*ln2):
//   z' = max(0.8*z + sb, 0),  sb = log2(1 + 2^dp)  via raw ex2/lg2 PTX.
//
// Noise prefetch at DISTANCE 2: at ~6.9 warps/SMSP a warp's per-step wall
// time (~370 cyc) is below the 577-cyc DRAM latency, so one in-flight load
// per warp cannot hide it; two can.
__global__ __launch_bounds__(64)
void acc_race_kernel(const float2* __restrict__ logits2,    // [B*2] float2
                     const float*  __restrict__ p_iscale,
                     const float*  __restrict__ p_leak,     // [4]
                     const float*  __restrict__ p_se,       // [4]
                     const float*  __restrict__ p_inh,
                     const float*  __restrict__ p_ns,
                     const float*  __restrict__ p_w,        // [1,1]
                     const float*  __restrict__ p_b,        // [1]
                     const float2* __restrict__ noise2,     // [T*B*2] float2
                     float2*       __restrict__ out2)       // [B*2] float2
{
    const int tid = blockIdx.x * blockDim.x + threadIdx.x;
    const int c0  = (tid & 1) * 2;       // classes {c0, c0+1}

    // ---- parameters (broadcast loads; transform once) ----
    const float iscale = *p_iscale;
    const float w      = *p_w;
    const float bias   = *p_b;
    const float inh    = fast_softplus(*p_inh);
    const float ns     = fast_softplus(*p_ns);
    const float K      = 0.2f * LN2_F;   // acc = K * z
    const float coefz0 = (fast_softplus(p_se[c0])   + inh - fast_softplus(p_leak[c0]))   * L2E_F * K;
    const float coefz1 = (fast_softplus(p_se[c0+1]) + inh - fast_softplus(p_leak[c0+1])) * L2E_F * K;
    const float inhz   = inh * L2E_F * K;
    const float nsp    = ns  * L2E_F;
    const float2 lg    = logits2[tid];
    const float evp0   = fmaf(fmaxf(lg.x * iscale, 0.0f), w, bias) * L2E_F;
    const float evp1   = fmaf(fmaxf(lg.y * iscale, 0.0f), w, bias) * L2E_F;
    const float ZTHRESH = THRESH / K;

    // ---- rollout state (z-domain), 2 independent elements ----
    float z0 = 0.0f, z1 = 0.0f;
    float cp0 = 0.0f, cc0 = 0.0f, tc0 = 0.0f;
    float cp1 = 0.0f, cc1 = 0.0f, tc1 = 0.0f;
    bool  cr0 = false, cr1 = false;

    // depth-2 noise prefetch pipeline (float2, coalesced 256B/warp)
    const float2* np = noise2 + tid;
    float2 nzA = *np;                    // for step t
    np += ROW_F2;
    float2 nzB = *np;                    // for step t+1

#define STEP_BODY(NZ)                                                         \
    do {                                                                      \
        /* acc-independent FMAs first: overlap the shuffle */                 \
        const float evn0 = fmaf(nsp, (NZ).x, evp0);                           \
        const float evn1 = fmaf(nsp, (NZ).y, evp1);                           \
        const float pair = z0 + z1;                                           \
        const float totz = pair + __shfl_xor_sync(0xffffffffu, pair, 1);      \
        const float x0 = fmaf(coefz0, z0, evn0);                              \
        const float x1 = fmaf(coefz1, z1, evn1);                              \
        const float dp0 = fmaf(-inhz, totz, x0);                              \
        const float dp1 = fmaf(-inhz, totz, x1);                              \
        const float sb0 = lg2_approx(1.0f + ex2_approx(dp0));                 \
        const float sb1 = lg2_approx(1.0f + ex2_approx(dp1));                 \
        z0 = fmaxf(fmaf(0.8f, z0, sb0), 0.0f);                                \
        z1 = fmaxf(fmaf(0.8f, z1, sb1), 0.0f);                                \
        /* crossing bookkeeping: overwrite until crossed, then freeze */      \
        const bool nc0 = !cr0;                                                \
        cp0 = nc0 ? cc0 : cp0;                                                \
        cc0 = nc0 ? z0  : cc0;                                                \
        tc0 = nc0 ? tc0 + 1.0f : tc0;                                         \
        cr0 = cr0 || (z0 >= ZTHRESH);                                         \
        const bool nc1 = !cr1;                                                \
        cp1 = nc1 ? cc1 : cp1;                                                \
        cc1 = nc1 ? z1  : cc1;                                                \
        tc1 = nc1 ? tc1 + 1.0f : tc1;                                         \
        cr1 = cr1 || (z1 >= ZTHRESH);                                         \
    } while (0)

    // 118 pipelined iterations (loads stay 2 ahead) + 2 drained tails
#pragma unroll 6
    for (int t = 0; t < TIME_STEPS - 2; ++t) {
        np += ROW_F2;
        const float2 nzC = *np;          // for step t+2
        STEP_BODY(nzA);
        nzA = nzB;
        nzB = nzC;
    }
    STEP_BODY(nzA);   // t = 118
    STEP_BODY(nzB);   // t = 119
#undef STEP_BODY

    // ---- epilogue: interpolate first-crossing time ----
    // acc = K*z; K cancels in the interpolation ratio.
    float t0, t1;
    if (cr0) {
        const float idx = tc0 - 1.0f;
        t0 = (idx > 0.0f)
               ? (idx - 1.0f + (ZTHRESH - cp0) / (cc0 - cp0 + EPS_F / K)) * DT_MS
               : 0.0f;
    } else {
        t0 = (float)TIME_STEPS * DT_MS;
    }
    if (cr1) {
        const float idx = tc1 - 1.0f;
        t1 = (idx > 0.0f)
               ? (idx - 1.0f + (ZTHRESH - cp1) / (cc1 - cp1 + EPS_F / K)) * DT_MS
               : 0.0f;
    } else {
        t1 = (float)TIME_STEPS * DT_MS;
    }

    out2[tid] = make_float2(t0 * 0.001f, t1 * 0.001f);
}

extern "C" void kernel_launch(void* const* d_in, const int* in_sizes, int n_in,
                              void* d_out, int out_size)
{
    const float2* logits = (const float2*)d_in[0];
    const float*  iscale = (const float*)d_in[1];
    const float*  leak   = (const float*)d_in[2];
    const float*  se     = (const float*)d_in[3];
    const float*  inh    = (const float*)d_in[4];
    const float*  ns     = (const float*)d_in[5];
    const float*  pw     = (const float*)d_in[6];
    const float*  pb     = (const float*)d_in[7];
    const float2* noise  = (const float2*)d_in[8];
    float2*       out    = (float2*)d_out;

    const int threads = 64;                  // fine-grained CTAs: 2048 blocks, good SM balance
    const int blocks  = NTHREADS / threads;  // 2048
    acc_race_kernel<<<blocks, threads>>>(logits, iscale, leak, se, inh, ns,
                                         pw, pb, noise, out);
}

// round 14
// speedup vs baseline: 1.2991x; 1.0513x over previous
#include <cuda_runtime.h>
#include <cuda_bf16.h>

// Problem constants (match reference)
#define N_CLASSES   4
#define TIME_STEPS  120
#define BATCH       65536
#define NTHREADS    (BATCH * 2)          // 131072: one thread per (batch, class-pair)
#define ROW_F2      (BATCH * 2)          // float2 elements per timestep row
#define DT_MS       10.0f
#define THRESH      0.5f
#define EPS_F       1e-9f
#define L2E_F       1.4426950408889634f  // log2(e)
#define LN2_F       0.6931471805599453f

__device__ __forceinline__ float ex2_approx(float x) {
    float r;
    asm("ex2.approx.ftz.f32 %0, %1;" : "=f"(r) : "f"(x));
    return r;
}
__device__ __forceinline__ float lg2_approx(float x) {
    float r;
    asm("lg2.approx.ftz.f32 %0, %1;" : "=f"(r) : "f"(x));
    return r;
}

__device__ __forceinline__ float fast_softplus(float x) {
    // parameter transform only (not in hot loop)
    float e = ex2_approx(-fabsf(x) * L2E_F);
    return fmaxf(x, 0.0f) + lg2_approx(1.0f + e) * LN2_F;
}

// One thread per (batch, class-pair); lane^1 partner holds the other pair, so
// the 4-class sum is FADD + shfl_xor + FADD.
//
// Noise prefetch at DEPTH 4. Little's law: streaming ~7 TB/s at 577-cycle
// DRAM latency requires ~2.2 MB in flight chip-wide. Depth-2 across 3072
// warps carried only 1.6 MB — both prior layouts pinned at ~4 TB/s for this
// reason. Depth-4 = 3.1 MB in flight.
__global__ __launch_bounds__(64)
void acc_race_kernel(const float2* __restrict__ logits2,    // [B*2] float2
                     const float*  __restrict__ p_iscale,
                     const float*  __restrict__ p_leak,     // [4]
                     const float*  __restrict__ p_se,       // [4]
                     const float*  __restrict__ p_inh,
                     const float*  __restrict__ p_ns,
                     const float*  __restrict__ p_w,        // [1,1]
                     const float*  __restrict__ p_b,        // [1]
                     const float2* __restrict__ noise2,     // [T*B*2] float2
                     float2*       __restrict__ out2)       // [B*2] float2
{
    const int tid = blockIdx.x * blockDim.x + threadIdx.x;
    const int c0  = (tid & 1) * 2;       // classes {c0, c0+1}

    // ---- parameters (broadcast loads; transform once) ----
    const float iscale = *p_iscale;
    const float w      = *p_w;
    const float bias   = *p_b;
    const float inh    = fast_softplus(*p_inh);
    const float ns     = fast_softplus(*p_ns);
    const float K      = 0.2f * LN2_F;   // acc = K * z
    const float coefz0 = (fast_softplus(p_se[c0])   + inh - fast_softplus(p_leak[c0]))   * L2E_F * K;
    const float coefz1 = (fast_softplus(p_se[c0+1]) + inh - fast_softplus(p_leak[c0+1])) * L2E_F * K;
    const float inhz   = inh * L2E_F * K;
    const float nsp    = ns  * L2E_F;
    const float2 lg    = logits2[tid];
    const float evp0   = fmaf(fmaxf(lg.x * iscale, 0.0f), w, bias) * L2E_F;
    const float evp1   = fmaf(fmaxf(lg.y * iscale, 0.0f), w, bias) * L2E_F;
    const float ZTHRESH = THRESH / K;

    // ---- rollout state (z-domain), 2 independent elements ----
    float z0 = 0.0f, z1 = 0.0f;
    float cp0 = 0.0f, cc0 = 0.0f, tc0 = 0.0f;
    float cp1 = 0.0f, cc1 = 0.0f, tc1 = 0.0f;
    bool  cr0 = false, cr1 = false;

    // depth-4 noise prefetch ring (float2, coalesced 256B/warp per load)
    const float2* np = noise2 + tid;
    float2 nzA = np[0];                       // step t
    float2 nzB = np[ROW_F2];                  // step t+1
    float2 nzC = np[2 * (size_t)ROW_F2];      // step t+2
    float2 nzD = np[3 * (size_t)ROW_F2];      // step t+3
    np += 3 * (size_t)ROW_F2;

#define STEP_BODY(NZ)                                                         \
    do {                                                                      \
        /* acc-independent FMAs first: overlap the shuffle */                 \
        const float evn0 = fmaf(nsp, (NZ).x, evp0);                           \
        const float evn1 = fmaf(nsp, (NZ).y, evp1);                           \
        const float pair = z0 + z1;                                           \
        const float totz = pair + __shfl_xor_sync(0xffffffffu, pair, 1);      \
        const float x0 = fmaf(coefz0, z0, evn0);                              \
        const float x1 = fmaf(coefz1, z1, evn1);                              \
        const float dp0 = fmaf(-inhz, totz, x0);                              \
        const float dp1 = fmaf(-inhz, totz, x1);                              \
        const float sb0 = lg2_approx(1.0f + ex2_approx(dp0));                 \
        const float sb1 = lg2_approx(1.0f + ex2_approx(dp1));                 \
        z0 = fmaxf(fmaf(0.8f, z0, sb0), 0.0f);                                \
        z1 = fmaxf(fmaf(0.8f, z1, sb1), 0.0f);                                \
        /* crossing bookkeeping: overwrite until crossed, then freeze */      \
        const bool nc0 = !cr0;                                                \
        cp0 = nc0 ? cc0 : cp0;                                                \
        cc0 = nc0 ? z0  : cc0;                                                \
        tc0 = nc0 ? tc0 + 1.0f : tc0;                                         \
        cr0 = cr0 || (z0 >= ZTHRESH);                                         \
        const bool nc1 = !cr1;                                                \
        cp1 = nc1 ? cc1 : cp1;                                                \
        cc1 = nc1 ? z1  : cc1;                                                \
        tc1 = nc1 ? tc1 + 1.0f : tc1;                                         \
        cr1 = cr1 || (z1 >= ZTHRESH);                                         \
    } while (0)

    // 116 pipelined iterations (loads stay 4 ahead; 116 = 4*29, unroll-4
    // makes the ring rotation free) + 4 drained tails
#pragma unroll 4
    for (int t = 0; t < TIME_STEPS - 4; ++t) {
        np += ROW_F2;
        const float2 nzE = *np;          // for step t+4
        STEP_BODY(nzA);
        nzA = nzB; nzB = nzC; nzC = nzD; nzD = nzE;
    }
    STEP_BODY(nzA);   // t = 116
    STEP_BODY(nzB);   // t = 117
    STEP_BODY(nzC);   // t = 118
    STEP_BODY(nzD);   // t = 119
#undef STEP_BODY

    // ---- epilogue: interpolate first-crossing time ----
    // acc = K*z; K cancels in the interpolation ratio.
    float t0, t1;
    if (cr0) {
        const float idx = tc0 - 1.0f;
        t0 = (idx > 0.0f)
               ? (idx - 1.0f + (ZTHRESH - cp0) / (cc0 - cp0 + EPS_F / K)) * DT_MS
               : 0.0f;
    } else {
        t0 = (float)TIME_STEPS * DT_MS;
    }
    if (cr1) {
        const float idx = tc1 - 1.0f;
        t1 = (idx > 0.0f)
               ? (idx - 1.0f + (ZTHRESH - cp1) / (cc1 - cp1 + EPS_F / K)) * DT_MS
               : 0.0f;
    } else {
        t1 = (float)TIME_STEPS * DT_MS;
    }

    out2[tid] = make_float2(t0 * 0.001f, t1 * 0.001f);
}

extern "C" void kernel_launch(void* const* d_in, const int* in_sizes, int n_in,
                              void* d_out, int out_size)
{
    const float2* logits = (const float2*)d_in[0];
    const float*  iscale = (const float*)d_in[1];
    const float*  leak   = (const float*)d_in[2];
    const float*  se     = (const float*)d_in[3];
    const float*  inh    = (const float*)d_in[4];
    const float*  ns     = (const float*)d_in[5];
    const float*  pw     = (const float*)d_in[6];
    const float*  pb     = (const float*)d_in[7];
    const float2* noise  = (const float2*)d_in[8];
    float2*       out    = (float2*)d_out;

    const int threads = 64;                  // 2048 blocks: good SM balance
    const int blocks  = NTHREADS / threads;  // 2048
    acc_race_kernel<<<blocks, threads>>>(logits, iscale, leak, se, inh, ns,
                                         pw, pb, noise, out);
}

// round 15
// speedup vs baseline: 1.3170x; 1.0137x over previous
#include <cuda_runtime.h>
#include <cuda_bf16.h>

// Problem constants (match reference)
#define N_CLASSES   4
#define TIME_STEPS  120
#define BATCH       65536
#define NTHREADS    (BATCH * N_CLASSES)   // 262144: one thread per (batch, class)
#define DT_MS       10.0f
#define THRESH      0.5f
#define EPS_F       1e-9f
#define L2E_F       1.4426950408889634f   // log2(e)
#define LN2_F       0.6931471805599453f

__device__ __forceinline__ float ex2_approx(float x) {
    float r;
    asm("ex2.approx.ftz.f32 %0, %1;" : "=f"(r) : "f"(x));
    return r;
}
__device__ __forceinline__ float lg2_approx(float x) {
    float r;
    asm("lg2.approx.ftz.f32 %0, %1;" : "=f"(r) : "f"(x));
    return r;
}

__device__ __forceinline__ float fast_softplus(float x) {
    // parameter transform only (not in hot loop)
    float e = ex2_approx(-fabsf(x) * L2E_F);
    return fmaxf(x, 0.0f) + lg2_approx(1.0f + e) * LN2_F;
}

// One thread per (batch, class): 8192 warps (max issue coverage; measured
// issue% tracks warp count). Quad sum via 2-shfl butterfly. z = acc/K domain,
// raw ex2/lg2 PTX softplus.
//
// Steps are processed in PAIRS: the first-crossing bookkeeping (the freeze of
// prev/cur bracketing values + step counter) runs once per pair on a 3-value
// history (zin, za, zb) — the epilogue disambiguates which step of the frozen
// pair crossed. This halves the bookkeeping issue cost, which was ~25% of the
// body. Noise loads for pair k+1 are issued at pair k (2 loads in flight,
// ~2-step slack > DRAM latency).
__global__ __launch_bounds__(128)
void acc_race_kernel(const float* __restrict__ logits,      // [B*4]
                     const float* __restrict__ p_iscale,
                     const float* __restrict__ p_leak,      // [4]
                     const float* __restrict__ p_se,        // [4]
                     const float* __restrict__ p_inh,
                     const float* __restrict__ p_ns,
                     const float* __restrict__ p_w,         // [1,1]
                     const float* __restrict__ p_b,         // [1]
                     const float* __restrict__ noise,       // [T*B*4]
                     float*       __restrict__ out)         // [B*4]
{
    const int tid = blockIdx.x * blockDim.x + threadIdx.x;
    const int c   = tid & (N_CLASSES - 1);

    // ---- parameters (broadcast loads; transform once) ----
    const float iscale = *p_iscale;
    const float w      = *p_w;
    const float bias   = *p_b;
    const float inh    = fast_softplus(*p_inh);
    const float ns     = fast_softplus(*p_ns);
    const float K      = 0.2f * LN2_F;            // acc = K * z
    const float coefz  = (fast_softplus(p_se[c]) + inh - fast_softplus(p_leak[c]))
                         * L2E_F * K;
    const float inhz   = inh * L2E_F * K;
    const float nsp    = ns  * L2E_F;
    const float evp    = fmaf(fmaxf(logits[tid] * iscale, 0.0f), w, bias) * L2E_F;
    const float ZTHRESH = THRESH / K;

    // ---- rollout state (z-domain) ----
    float z  = 0.0f;
    float s0 = 0.0f, s1 = 0.0f, s2 = 0.0f;  // frozen history: z before pair, after step a, after step b
    float tcp = 0.0f;                        // pairs elapsed while uncrossed (incl. crossing pair)
    bool  cr  = false;

    // pair-ahead noise prefetch (2 loads in flight)
    const float* np = noise + tid;
    float nzA = np[0];             // pair step a
    float nzB = np[NTHREADS];      // pair step b
    np += NTHREADS;

#define HALF_STEP(NZ)                                                         \
    do {                                                                      \
        const float q  = z + __shfl_xor_sync(0xffffffffu, z, 1);              \
        const float tot = q + __shfl_xor_sync(0xffffffffu, q, 2);             \
        const float evn = fmaf(nsp, (NZ), evp);                               \
        const float x  = fmaf(coefz, z, evn);                                 \
        const float dp = fmaf(-inhz, tot, x);                                 \
        const float sb = lg2_approx(1.0f + ex2_approx(dp));                   \
        z = fmaxf(fmaf(0.8f, z, sb), 0.0f);                                   \
    } while (0)

#define PAIR_BODY(NA, NB)                                                     \
    do {                                                                      \
        const float zin = z;                                                  \
        HALF_STEP(NA);                                                        \
        const float za = z;                                                   \
        HALF_STEP(NB);                                                        \
        const float zb = z;                                                   \
        const bool nc = !cr;                                                  \
        s0  = nc ? zin : s0;                                                  \
        s1  = nc ? za  : s1;                                                  \
        s2  = nc ? zb  : s2;                                                  \
        tcp = nc ? tcp + 1.0f : tcp;                                          \
        cr  = cr || (fmaxf(za, zb) >= ZTHRESH);                               \
    } while (0)

    // 59 prefetching pair-iterations + 1 drained tail pair  (60 pairs = 120 steps)
#pragma unroll 3
    for (int k = 0; k < TIME_STEPS / 2 - 1; ++k) {
        np += NTHREADS;
        const float nzC = *np;     // next pair step a
        np += NTHREADS;
        const float nzD = *np;     // next pair step b
        PAIR_BODY(nzA, nzB);
        nzA = nzC;
        nzB = nzD;
    }
    PAIR_BODY(nzA, nzB);           // last pair, no prefetch
#undef PAIR_BODY
#undef HALF_STEP

    // ---- epilogue: locate crossing inside the frozen pair, interpolate ----
    float tm;
    if (cr) {
        const bool  fa   = (s1 >= ZTHRESH);          // crossed on first step of pair?
        const float prev = fa ? s0 : s1;
        const float cur  = fa ? s1 : s2;
        const float idx  = 2.0f * (tcp - 1.0f) + (fa ? 0.0f : 1.0f);
        tm = (idx > 0.0f)
               ? (idx - 1.0f + (ZTHRESH - prev) / (cur - prev + EPS_F / K)) * DT_MS
               : 0.0f;                               // crossed at step 0
    } else {
        tm = (float)TIME_STEPS * DT_MS;              // never crossed: 1200 ms
    }
    out[tid] = tm * 0.001f;                          // -> seconds

}

extern "C" void kernel_launch(void* const* d_in, const int* in_sizes, int n_in,
                              void* d_out, int out_size)
{
    const float* logits = (const float*)d_in[0];
    const float* iscale = (const float*)d_in[1];
    const float* leak   = (const float*)d_in[2];
    const float* se     = (const float*)d_in[3];
    const float* inh    = (const float*)d_in[4];
    const float* ns     = (const float*)d_in[5];
    const float* pw     = (const float*)d_in[6];
    const float* pb     = (const float*)d_in[7];
    const float* noise  = (const float*)d_in[8];
    float*       out    = (float*)d_out;

    const int threads = 128;
    const int blocks  = NTHREADS / threads;   // 2048
    acc_race_kernel<<<blocks, threads>>>(logits, iscale, leak, se, inh, ns,
                                         pw, pb, noise, out);
}

// round 17
// speedup vs baseline: 1.6091x; 1.2218x over previous
#include <cuda_runtime.h>
#include <cuda_bf16.h>

// Problem constants (match reference)
#define N_CLASSES   4
#define TIME_STEPS  120
#define BATCH       65536
#define NTHREADS    (BATCH * N_CLASSES)   // 262144: one thread per (batch, class)
#define DT_MS       10.0f
#define THRESH      0.5f
#define EPS_F       1e-9f
#define L2E_F       1.4426950408889634f   // log2(e)
#define LN2_F       0.6931471805599453f

__device__ __forceinline__ float ex2_approx(float x) {
    float r;
    asm("ex2.approx.ftz.f32 %0, %1;" : "=f"(r) : "f"(x));
    return r;
}
__device__ __forceinline__ float lg2_approx(float x) {
    float r;
    asm("lg2.approx.ftz.f32 %0, %1;" : "=f"(r) : "f"(x));
    return r;
}

__device__ __forceinline__ float fast_softplus(float x) {
    // parameter transform only (not in hot loop)
    float e = ex2_approx(-fabsf(x) * L2E_F);
    return fmaxf(x, 0.0f) + lg2_approx(1.0f + e) * LN2_F;
}

// One thread per (batch, class); lane quad 4b..4b+3 holds the 4 classes of
// batch element b; quad sum via 2-shfl butterfly (f32 redux is sm_103+ only).
// z = acc/K domain, raw ex2/lg2 PTX softplus, pair-step crossing bookkeeping.
//
// EARLY EXIT: once a lane crosses, all its output state is frozen; when every
// lane of the warp has crossed (__all_sync), the remaining timesteps are dead
// work and the warp leaves the loop. Output is bit-identical by construction.
__global__ __launch_bounds__(64)
void acc_race_kernel(const float* __restrict__ logits,      // [B*4]
                     const float* __restrict__ p_iscale,
                     const float* __restrict__ p_leak,      // [4]
                     const float* __restrict__ p_se,        // [4]
                     const float* __restrict__ p_inh,
                     const float* __restrict__ p_ns,
                     const float* __restrict__ p_w,         // [1,1]
                     const float* __restrict__ p_b,         // [1]
                     const float* __restrict__ noise,       // [T*B*4]
                     float*       __restrict__ out)         // [B*4]
{
    const int tid = blockIdx.x * blockDim.x + threadIdx.x;
    const int c   = tid & (N_CLASSES - 1);

    // ---- parameters (broadcast loads; transform once) ----
    const float iscale = *p_iscale;
    const float w      = *p_w;
    const float bias   = *p_b;
    const float inh    = fast_softplus(*p_inh);
    const float ns     = fast_softplus(*p_ns);
    const float K      = 0.2f * LN2_F;            // acc = K * z
    const float coefz  = (fast_softplus(p_se[c]) + inh - fast_softplus(p_leak[c]))
                         * L2E_F * K;
    const float inhz   = inh * L2E_F * K;
    const float nsp    = ns  * L2E_F;
    const float evp    = fmaf(fmaxf(logits[tid] * iscale, 0.0f), w, bias) * L2E_F;
    const float ZTHRESH = THRESH / K;

    // ---- rollout state (z-domain) ----
    float z  = 0.0f;
    float s0 = 0.0f, s1 = 0.0f, s2 = 0.0f;  // frozen bracket: z before pair, after a, after b
    float tcp = 0.0f;                        // pairs elapsed while uncrossed (incl. crossing pair)
    bool  cr  = false;

    // two-pair-ahead noise prefetch (4 loads in flight)
    const float* np = noise + tid;
    float nzA = np[0];                        // pair k,   step a
    float nzB = np[NTHREADS];                 // pair k,   step b
    float nzC = np[2 * (size_t)NTHREADS];     // pair k+1, step a
    float nzD = np[3 * (size_t)NTHREADS];     // pair k+1, step b
    np += 3 * (size_t)NTHREADS;

#define HALF_STEP(NZ)                                                         \
    do {                                                                      \
        const float q   = z + __shfl_xor_sync(0xffffffffu, z, 1);             \
        const float tot = q + __shfl_xor_sync(0xffffffffu, q, 2);             \
        const float evn = fmaf(nsp, (NZ), evp);                               \
        const float x   = fmaf(coefz, z, evn);                                \
        const float dp  = fmaf(-inhz, tot, x);                                \
        const float sb  = lg2_approx(1.0f + ex2_approx(dp));                  \
        z = fmaxf(fmaf(0.8f, z, sb), 0.0f);                                   \
    } while (0)

#define PAIR_BODY(NA, NB)                                                     \
    do {                                                                      \
        const float zin = z;                                                  \
        HALF_STEP(NA);                                                        \
        const float za = z;                                                   \
        HALF_STEP(NB);                                                        \
        const float zb = z;                                                   \
        const bool nc = !cr;                                                  \
        s0  = nc ? zin : s0;                                                  \
        s1  = nc ? za  : s1;                                                  \
        s2  = nc ? zb  : s2;                                                  \
        tcp = nc ? tcp + 1.0f : tcp;                                          \
        cr  = cr || (fmaxf(za, zb) >= ZTHRESH);                               \
    } while (0)

    // 58 pipelined pair-iterations (loads 2 pairs ahead) + 2 drained pairs.
    // Early exit when the whole warp has crossed: all output state is frozen,
    // remaining steps are dead work.
#pragma unroll 2
    for (int k = 0; k < TIME_STEPS / 2 - 2; ++k) {
        np += NTHREADS;
        const float nzE = *np;     // pair k+2, step a
        np += NTHREADS;
        const float nzF = *np;     // pair k+2, step b
        PAIR_BODY(nzA, nzB);
        if (__all_sync(0xffffffffu, cr)) goto done;
        nzA = nzC; nzB = nzD; nzC = nzE; nzD = nzF;
    }
    PAIR_BODY(nzA, nzB);           // pair 58
    if (!__all_sync(0xffffffffu, cr)) {
        PAIR_BODY(nzC, nzD);       // pair 59
    }
done: ;
#undef PAIR_BODY
#undef HALF_STEP

    // ---- epilogue: locate crossing inside the frozen pair, interpolate ----
    float tm;
    if (cr) {
        const bool  fa   = (s1 >= ZTHRESH);          // crossed on first step of pair?
        const float prev = fa ? s0 : s1;
        const float cur  = fa ? s1 : s2;
        const float idx  = 2.0f * (tcp - 1.0f) + (fa ? 0.0f : 1.0f);
        tm = (idx > 0.0f)
               ? (idx - 1.0f + (ZTHRESH - prev) / (cur - prev + EPS_F / K)) * DT_MS
               : 0.0f;                               // crossed at step 0
    } else {
        tm = (float)TIME_STEPS * DT_MS;              // never crossed: 1200 ms
    }
    out[tid] = tm * 0.001f;                          // -> seconds
}

extern "C" void kernel_launch(void* const* d_in, const int* in_sizes, int n_in,
                              void* d_out, int out_size)
{
    const float* logits = (const float*)d_in[0];
    const float* iscale = (const float*)d_in[1];
    const float* leak   = (const float*)d_in[2];
    const float* se     = (const float*)d_in[3];
    const float* inh    = (const float*)d_in[4];
    const float* ns     = (const float*)d_in[5];
    const float* pw     = (const float*)d_in[6];
    const float* pb     = (const float*)d_in[7];
    const float* noise  = (const float*)d_in[8];
    float*       out    = (float*)d_out;

    const int threads = 64;                  // 4096 CTAs: 27.7/SM, ~3.6% tail imbalance
    const int blocks  = NTHREADS / threads;
    acc_race_kernel<<<blocks, threads>>>(logits, iscale, leak, se, inh, ns,
                                         pw, pb, noise, out);
}